// round 8
// baseline (speedup 1.0000x reference)
#include <cuda_runtime.h>
#include <stdint.h>

#define SRC_SIZE 262144
#define DST_SIZE 65536
#define N_EDGES  2097152
#define BATCH    4
#define FEAT     32

// Every dst segment padded to a multiple of 8 records.
#define PAD_EDGES (N_EDGES + 7 * DST_SIZE + 64)

#define SCAN_BLOCKS 256
#define SCAN_CHUNK  256   // DST_SIZE / SCAN_BLOCKS

#define FIX_SCALE 16777216.0f       // 2^24
#define INV_FIX   (1.0f / 16777216.0f)

// ---------------------------------------------------------------------------
// Scratch
// ---------------------------------------------------------------------------
__device__ unsigned long long g_hist[DST_SIZE];   // {count:u32 | fixed24(sum w):u32}
__device__ float4         g_meta[DST_SIZE];       // {off(bits), cnt(bits), inv, 0}
__device__ unsigned short g_rank[N_EDGES];        // edge's arrival rank within its dst
__device__ int2           g_sorted[PAD_EDGES];    // {src, __float_as_int(w)}

// ---------------------------------------------------------------------------
// K1: histogram; returned old count = edge's rank within its dst.
// ---------------------------------------------------------------------------
__global__ void k_hist(const float* __restrict__ weights,
                       const int* __restrict__ dst_idx, int n_edges) {
    int e = blockIdx.x * blockDim.x + threadIdx.x;
    if (e < n_edges) {
        int d = __ldg(&dst_idx[e]);
        float w = __ldg(&weights[e]);
        unsigned long long v =
            (1ULL << 32) | (unsigned long long)(unsigned int)(w * FIX_SCALE);
        unsigned long long old = atomicAdd(&g_hist[d], v);
        g_rank[e] = (unsigned short)(old >> 32);
    }
}

// ---------------------------------------------------------------------------
// K2: merged scan over counts padded to multiples of 8. Emits g_meta and
// fills pad slots of g_sorted with {0, 0.0f} dummy edges.
// ---------------------------------------------------------------------------
__global__ void k_scan() {
    __shared__ int sh[8];
    __shared__ int shp[8];
    __shared__ int s_prefix;

    const int t = threadIdx.x;
    const int lane = t & 31;
    const int warp = t >> 5;
    const int nprev = blockIdx.x * SCAN_CHUNK;

    int p0 = 0, p1 = 0, p2 = 0, p3 = 0;
    int i = t;
    for (; i + 768 < nprev; i += 1024) {
        p0 += ((int)(g_hist[i]       >> 32) + 7) & ~7;
        p1 += ((int)(g_hist[i + 256] >> 32) + 7) & ~7;
        p2 += ((int)(g_hist[i + 512] >> 32) + 7) & ~7;
        p3 += ((int)(g_hist[i + 768] >> 32) + 7) & ~7;
    }
    for (; i < nprev; i += 256) p0 += ((int)(g_hist[i] >> 32) + 7) & ~7;
    int p = (p0 + p1) + (p2 + p3);
#pragma unroll
    for (int off = 16; off > 0; off >>= 1)
        p += __shfl_down_sync(0xFFFFFFFFu, p, off);
    if (lane == 0) shp[warp] = p;
    __syncthreads();
    if (t == 0) {
        int acc = 0;
#pragma unroll
        for (int k = 0; k < 8; k++) acc += shp[k];
        s_prefix = acc;
    }

    const int d = nprev + t;
    unsigned long long h = g_hist[d];
    int c = (int)(h >> 32);
    int cp = (c + 7) & ~7;
    float norm = (float)(unsigned int)(h & 0xFFFFFFFFULL) * INV_FIX;

    int v = cp;
#pragma unroll
    for (int off = 1; off < 32; off <<= 1) {
        int n = __shfl_up_sync(0xFFFFFFFFu, v, off);
        if (lane >= off) v += n;
    }
    if (lane == 31) sh[warp] = v;
    __syncthreads();
    if (warp == 0) {
        int u = (lane < 8) ? sh[lane] : 0;
#pragma unroll
        for (int off = 1; off < 8; off <<= 1) {
            int n = __shfl_up_sync(0xFFFFFFFFu, u, off);
            if (lane >= off) u += n;
        }
        if (lane < 8) sh[lane] = u;
    }
    __syncthreads();
    int incl = v + ((warp > 0) ? sh[warp - 1] : 0);

    int off = s_prefix + incl - cp;
    float4 m;
    m.x = __int_as_float(off);
    m.y = __int_as_float(c);
    m.z = 1.0f / (norm + 1e-8f);
    m.w = 0.0f;
    g_meta[d] = m;

    // Fill pad slots (scatter never touches these; reduce reads w=0).
    for (int k = c; k < cp; k++)
        g_sorted[off + k] = make_int2(0, 0);
}

// ---------------------------------------------------------------------------
// K3: atomic-free scatter: pos = meta.off + rank[edge]
// ---------------------------------------------------------------------------
__global__ void k_scatter(const float* __restrict__ weights,
                          const int* __restrict__ src_idx,
                          const int* __restrict__ dst_idx, int n_edges) {
    int e = blockIdx.x * blockDim.x + threadIdx.x;
    if (e < n_edges) {
        int d = __ldg(&dst_idx[e]);
        int off = __float_as_int(__ldg(&g_meta[d].x));
        int pos = off + (int)g_rank[e];
        int2 p;
        p.x = __ldg(&src_idx[e]);
        p.y = __float_as_int(__ldg(&weights[e]));
        g_sorted[pos] = p;
    }
}

// ---------------------------------------------------------------------------
// K4: segmented reduction. Batch-phased (one warp per (batch,dst), grid
// batch-major). Lane = (es=lane>>3, fg=lane&7). Groups of 8 edges: each lane
// loads int4 = 2 records (edges 2es, 2es+1) and gathers 2 full 128B rows.
// Segments padded to x8 => uniform trips, no remainder. Unroll 2 groups.
// ---------------------------------------------------------------------------
__global__ void __launch_bounds__(128, 10)
k_reduce(const float* __restrict__ x, float* __restrict__ out) {
    const int gw   = blockIdx.x * 4 + (threadIdx.x >> 5);  // global warp id
    const int b    = gw >> 16;                              // batch (batch-major)
    const int dst  = gw & (DST_SIZE - 1);
    const int lane = threadIdx.x & 31;
    const int es   = lane >> 3;   // record-pair slot 0..3
    const int fg   = lane & 7;    // float4 group 0..7

    const float4 meta = __ldg(&g_meta[dst]);
    const int off = __float_as_int(meta.x);
    const int cnt = __float_as_int(meta.y);
    const float inv = meta.z;
    const int ngroups = (cnt + 7) >> 3;   // groups of 8 edges

    const float* xb = x + (size_t)b * (SRC_SIZE * FEAT) + fg * 4;

    float ax = 0.f, ay = 0.f, az = 0.f, aw = 0.f;
    float bx = 0.f, by = 0.f, bz = 0.f, bw = 0.f;

    int j = off + 2 * es;   // record index of this lane's first record
    int i = 0;
    for (; i + 1 < ngroups; i += 2, j += 16) {
        int4 r0 = __ldcs((const int4*)&g_sorted[j]);       // edges 2es, 2es+1
        int4 r1 = __ldcs((const int4*)&g_sorted[j + 8]);   // next group
        float4 v00 = *(const float4*)(xb + (size_t)r0.x * FEAT);
        float4 v01 = *(const float4*)(xb + (size_t)r0.z * FEAT);
        float4 v10 = *(const float4*)(xb + (size_t)r1.x * FEAT);
        float4 v11 = *(const float4*)(xb + (size_t)r1.z * FEAT);
        float w00 = __int_as_float(r0.y), w01 = __int_as_float(r0.w);
        float w10 = __int_as_float(r1.y), w11 = __int_as_float(r1.w);
        ax += w00 * v00.x; ay += w00 * v00.y; az += w00 * v00.z; aw += w00 * v00.w;
        bx += w01 * v01.x; by += w01 * v01.y; bz += w01 * v01.z; bw += w01 * v01.w;
        ax += w10 * v10.x; ay += w10 * v10.y; az += w10 * v10.z; aw += w10 * v10.w;
        bx += w11 * v11.x; by += w11 * v11.y; bz += w11 * v11.z; bw += w11 * v11.w;
    }
    if (i < ngroups) {
        int4 r0 = __ldcs((const int4*)&g_sorted[j]);
        float4 v00 = *(const float4*)(xb + (size_t)r0.x * FEAT);
        float4 v01 = *(const float4*)(xb + (size_t)r0.z * FEAT);
        float w00 = __int_as_float(r0.y), w01 = __int_as_float(r0.w);
        ax += w00 * v00.x; ay += w00 * v00.y; az += w00 * v00.z; aw += w00 * v00.w;
        bx += w01 * v01.x; by += w01 * v01.y; bz += w01 * v01.z; bw += w01 * v01.w;
    }

    ax += bx; ay += by; az += bz; aw += bw;

    // Fold the 4 es-slots (lanes fg, fg+8, fg+16, fg+24).
#pragma unroll
    for (int m = 8; m <= 16; m <<= 1) {
        ax += __shfl_xor_sync(0xFFFFFFFFu, ax, m);
        ay += __shfl_xor_sync(0xFFFFFFFFu, ay, m);
        az += __shfl_xor_sync(0xFFFFFFFFu, az, m);
        aw += __shfl_xor_sync(0xFFFFFFFFu, aw, m);
    }

    if (es == 0) {
        float4 r = make_float4(ax * inv, ay * inv, az * inv, aw * inv);
        float* o = out + (size_t)b * (DST_SIZE * FEAT) + (size_t)dst * FEAT + fg * 4;
        *(float4*)o = r;
    }
}

// ---------------------------------------------------------------------------
// kernel_launch
// ---------------------------------------------------------------------------
extern "C" void kernel_launch(void* const* d_in, const int* in_sizes, int n_in,
                              void* d_out, int out_size) {
    const float* x       = (const float*)d_in[0];
    const float* weights = (const float*)d_in[1];
    const int*   src_idx = (const int*)d_in[2];
    const int*   dst_idx = (const int*)d_in[3];
    float*       out     = (float*)d_out;
    const int n_edges = in_sizes[1];

    void* hist_ptr = nullptr;
    cudaGetSymbolAddress(&hist_ptr, g_hist);
    cudaMemsetAsync(hist_ptr, 0, DST_SIZE * sizeof(unsigned long long), 0);

    k_hist<<<(n_edges + 255) / 256, 256>>>(weights, dst_idx, n_edges);
    k_scan<<<SCAN_BLOCKS, SCAN_CHUNK>>>();
    k_scatter<<<(n_edges + 255) / 256, 256>>>(weights, src_idx, dst_idx, n_edges);
    // BATCH * DST_SIZE warps, 4 warps/block, batch-major ordering.
    k_reduce<<<(BATCH * DST_SIZE) / 4, 128>>>(x, out);
}